// round 1
// baseline (speedup 1.0000x reference)
#include <cuda_runtime.h>
#include <cuda_bf16.h>
#include <cstdint>

// Problem dims (fixed by the dataset)
#define M_TOT 8192   // B*S = 4*2048
#define K_TOT 4096
#define N_TOT 4096

// GEMM tiling
#define BM 128
#define BN 128
#define BK 32
#define STAGES 4
#define THREADS 256

// Shared-memory tile layout: 128 rows x (32 bf16 data + 8 bf16 pad) = 80B rows.
// 80 mod 128 cycles through 8 distinct 16B banks -> ldmatrix conflict-free.
#define ROW_BYTES 80
#define TILE_BYTES (128 * ROW_BYTES)    // 10240
#define STAGE_BYTES (2 * TILE_BYTES)    // 20480 (A + B)
#define SMEM_TOTAL (STAGES * STAGE_BYTES) // 81920

// Scratch: centered-quantized activations and centered weights in bf16.
// (|xc| <= 128, |wc| <= 255 : exactly representable in bf16)
__device__ __align__(16) __nv_bfloat16 g_Xq[(size_t)M_TOT * K_TOT];
__device__ __align__(16) __nv_bfloat16 g_Wc[(size_t)N_TOT * K_TOT];

// ---------------------------------------------------------------------------
// Kernel 1: quantize activations. xc = clip(rint(x/s), -zp, 255-zp), bf16.
// One float4 per thread.
// ---------------------------------------------------------------------------
__global__ void quant_x_kernel(const float* __restrict__ x,
                               const float* __restrict__ act_scale,
                               const int* __restrict__ act_zp) {
    size_t idx = (size_t)blockIdx.x * blockDim.x + threadIdx.x; // float4 index
    const float s  = act_scale[0];
    const float zp = (float)act_zp[0];
    const float lo = 0.0f - zp;
    const float hi = 255.0f - zp;

    float4 v = ((const float4*)x)[idx];
    float q0 = fminf(fmaxf(rintf(v.x / s), lo), hi);
    float q1 = fminf(fmaxf(rintf(v.y / s), lo), hi);
    float q2 = fminf(fmaxf(rintf(v.z / s), lo), hi);
    float q3 = fminf(fmaxf(rintf(v.w / s), lo), hi);

    __nv_bfloat162 p0 = __floats2bfloat162_rn(q0, q1);
    __nv_bfloat162 p1 = __floats2bfloat162_rn(q2, q3);
    uint2 u;
    u.x = *reinterpret_cast<unsigned*>(&p0);
    u.y = *reinterpret_cast<unsigned*>(&p1);
    ((uint2*)g_Xq)[idx] = u;
}

// ---------------------------------------------------------------------------
// Kernel 2: center weights. wc[o,i] = (float)(w_q[o,i] - w_zp[o]), bf16.
// One int4 (4 int32 values) per thread. K_TOT/4 = 1024 int4 per output row.
// ---------------------------------------------------------------------------
__global__ void conv_w_kernel(const int* __restrict__ wq,
                              const int* __restrict__ wzp) {
    size_t idx = (size_t)blockIdx.x * blockDim.x + threadIdx.x; // int4 index
    int4 v = ((const int4*)wq)[idx];
    float zp = (float)wzp[idx >> 10]; // idx*4 / 4096

    __nv_bfloat162 p0 = __floats2bfloat162_rn((float)v.x - zp, (float)v.y - zp);
    __nv_bfloat162 p1 = __floats2bfloat162_rn((float)v.z - zp, (float)v.w - zp);
    uint2 u;
    u.x = *reinterpret_cast<unsigned*>(&p0);
    u.y = *reinterpret_cast<unsigned*>(&p1);
    ((uint2*)g_Wc)[idx] = u;
}

// ---------------------------------------------------------------------------
// Kernel 3: bf16 GEMM, out[m,o] = sa*ws[o]*dot(xc[m,:], wc[o,:]) + bias[o]
// 128x128 block tile, BK=32, 4-stage cp.async pipeline, mma.sync.m16n8k16.
// 8 warps: 2 (M) x 4 (N); warp tile 64x32 = 4x4 m16n8 mma tiles.
// ---------------------------------------------------------------------------
__global__ void __launch_bounds__(THREADS, 2)
gemm_kernel(const float* __restrict__ ws,
            const float* __restrict__ bias,
            const float* __restrict__ act_scale,
            float* __restrict__ out) {
    extern __shared__ char smem[];
    const uint32_t smem_base = (uint32_t)__cvta_generic_to_shared(smem);

    const int tid    = threadIdx.x;
    const int lane   = tid & 31;
    const int wid    = tid >> 5;
    const int warp_m = wid & 1;   // 0..1 -> 64 rows each
    const int warp_n = wid >> 1;  // 0..3 -> 32 cols each
    const int bm = blockIdx.y;
    const int bn = blockIdx.x;

    const __nv_bfloat16* Ag = g_Xq + (size_t)bm * BM * K_TOT;
    const __nv_bfloat16* Bg = g_Wc + (size_t)bn * BN * K_TOT;

    // Per-thread cp.async coords: chunk c = tid + i*256; row = c/4, col16 = c%4
    const int ld_row0 = tid >> 2;
    const int ld_col  = tid & 3;

    // ldmatrix lane offsets (byte offsets within a tile)
    // A: row = warp_m*64 + mi*16 + (lane&15); byte col = (lane>>4)*16 + k16*32
    const uint32_t aoff = (uint32_t)(warp_m * 64 + (lane & 15)) * ROW_BYTES
                        + ((lane >> 4) * 16);
    // B: nrow = warp_n*32 + nj*16 + (lane&7) + ((lane>>4)<<3)
    //    byte col = ((lane>>3)&1)*16 + k16*32
    const uint32_t boff = (uint32_t)(warp_n * 32 + (lane & 7) + ((lane >> 4) << 3)) * ROW_BYTES
                        + (((lane >> 3) & 1) * 16);

    float acc[4][4][4];
    #pragma unroll
    for (int i = 0; i < 4; i++)
        #pragma unroll
        for (int j = 0; j < 4; j++)
            #pragma unroll
            for (int k = 0; k < 4; k++) acc[i][j][k] = 0.0f;

    auto load_stage = [&](int stage, int kt) {
        const uint32_t sa = smem_base + stage * STAGE_BYTES;
        const uint32_t sb = sa + TILE_BYTES;
        const int k0 = kt * BK;
        #pragma unroll
        for (int i = 0; i < 2; i++) {
            const int row = ld_row0 + i * 64;
            const __nv_bfloat16* gA = Ag + (size_t)row * K_TOT + k0 + ld_col * 8;
            const uint32_t dA = sa + (uint32_t)row * ROW_BYTES + ld_col * 16;
            asm volatile("cp.async.cg.shared.global [%0], [%1], 16;\n"
                         :: "r"(dA), "l"(gA));
            const __nv_bfloat16* gB = Bg + (size_t)row * K_TOT + k0 + ld_col * 8;
            const uint32_t dB = sb + (uint32_t)row * ROW_BYTES + ld_col * 16;
            asm volatile("cp.async.cg.shared.global [%0], [%1], 16;\n"
                         :: "r"(dB), "l"(gB));
        }
    };

    // Prologue: prefetch STAGES-1 tiles
    #pragma unroll
    for (int s = 0; s < STAGES - 1; s++) {
        load_stage(s, s);
        asm volatile("cp.async.commit_group;\n");
    }
    asm volatile("cp.async.wait_group %0;\n" :: "n"(STAGES - 2));
    __syncthreads();

    const int NKT = K_TOT / BK; // 128
    for (int kt = 0; kt < NKT; kt++) {
        const int stage = kt & (STAGES - 1);
        const uint32_t sa = smem_base + stage * STAGE_BYTES;
        const uint32_t sb = sa + TILE_BYTES;

        #pragma unroll
        for (int k16 = 0; k16 < 2; k16++) {
            uint32_t a[4][4], b[2][4];
            #pragma unroll
            for (int mi = 0; mi < 4; mi++) {
                const uint32_t addr = sa + aoff + mi * (16 * ROW_BYTES) + k16 * 32;
                asm volatile(
                    "ldmatrix.sync.aligned.m8n8.x4.shared.b16 {%0,%1,%2,%3}, [%4];\n"
                    : "=r"(a[mi][0]), "=r"(a[mi][1]), "=r"(a[mi][2]), "=r"(a[mi][3])
                    : "r"(addr));
            }
            #pragma unroll
            for (int nj = 0; nj < 2; nj++) {
                const uint32_t addr = sb + boff + nj * (16 * ROW_BYTES) + k16 * 32;
                asm volatile(
                    "ldmatrix.sync.aligned.m8n8.x4.shared.b16 {%0,%1,%2,%3}, [%4];\n"
                    : "=r"(b[nj][0]), "=r"(b[nj][1]), "=r"(b[nj][2]), "=r"(b[nj][3])
                    : "r"(addr));
            }
            #pragma unroll
            for (int mi = 0; mi < 4; mi++) {
                #pragma unroll
                for (int ni = 0; ni < 4; ni++) {
                    const uint32_t b0 = b[ni >> 1][(ni & 1) * 2 + 0];
                    const uint32_t b1 = b[ni >> 1][(ni & 1) * 2 + 1];
                    float* c = acc[mi][ni];
                    asm volatile(
                        "mma.sync.aligned.m16n8k16.row.col.f32.bf16.bf16.f32 "
                        "{%0,%1,%2,%3}, {%4,%5,%6,%7}, {%8,%9}, {%0,%1,%2,%3};\n"
                        : "+f"(c[0]), "+f"(c[1]), "+f"(c[2]), "+f"(c[3])
                        : "r"(a[mi][0]), "r"(a[mi][1]), "r"(a[mi][2]), "r"(a[mi][3]),
                          "r"(b0), "r"(b1));
                }
            }
        }

        const int nkt = kt + STAGES - 1;
        if (nkt < NKT) load_stage(nkt & (STAGES - 1), nkt);
        asm volatile("cp.async.commit_group;\n");
        asm volatile("cp.async.wait_group %0;\n" :: "n"(STAGES - 2));
        __syncthreads();
    }

    // Epilogue: out = acc * (sa * ws[o]) + bias[o]
    const float sa_s = act_scale[0];
    const int row_base = bm * BM + warp_m * 64;
    const int col_base = bn * BN + warp_n * 32;
    #pragma unroll
    for (int ni = 0; ni < 4; ni++) {
        const int col = col_base + ni * 8 + (lane & 3) * 2;
        const float2 wsv = *(const float2*)(ws + col);
        const float2 bv  = *(const float2*)(bias + col);
        const float s0 = sa_s * wsv.x;
        const float s1 = sa_s * wsv.y;
        #pragma unroll
        for (int mi = 0; mi < 4; mi++) {
            const int r0 = row_base + mi * 16 + (lane >> 2);
            const float* c = acc[mi][ni];
            float2 o0, o1;
            o0.x = c[0] * s0 + bv.x;  o0.y = c[1] * s1 + bv.y;
            o1.x = c[2] * s0 + bv.x;  o1.y = c[3] * s1 + bv.y;
            *(float2*)(out + (size_t)r0 * N_TOT + col) = o0;
            *(float2*)(out + (size_t)(r0 + 8) * N_TOT + col) = o1;
        }
    }
}

// ---------------------------------------------------------------------------
// Launch. Inputs (metadata order): x, weight_q, weight_scales,
// weight_zero_points, act_scales, act_zero_points, bias. Output: float32.
// ---------------------------------------------------------------------------
extern "C" void kernel_launch(void* const* d_in, const int* in_sizes, int n_in,
                              void* d_out, int out_size) {
    const float* x    = (const float*)d_in[0];
    const int*   wq   = (const int*)d_in[1];
    const float* wsc  = (const float*)d_in[2];
    const int*   wzp  = (const int*)d_in[3];
    const float* asc  = (const float*)d_in[4];
    const int*   azp  = (const int*)d_in[5];
    const float* bias = (const float*)d_in[6];
    float* out = (float*)d_out;

    // 1) quantize activations: M*K/4 float4s
    {
        const size_t n4 = (size_t)M_TOT * K_TOT / 4;
        quant_x_kernel<<<(unsigned)(n4 / 256), 256>>>(x, asc, azp);
    }
    // 2) center weights: N*K/4 int4s
    {
        const size_t n4 = (size_t)N_TOT * K_TOT / 4;
        conv_w_kernel<<<(unsigned)(n4 / 256), 256>>>(wq, wzp);
    }
    // 3) GEMM + epilogue
    {
        cudaFuncSetAttribute(gemm_kernel,
                             cudaFuncAttributeMaxDynamicSharedMemorySize,
                             SMEM_TOTAL);
        dim3 grid(N_TOT / BN, M_TOT / BM); // (32, 64)
        gemm_kernel<<<grid, THREADS, SMEM_TOTAL>>>(wsc, bias, asc, out);
    }
}